// round 1
// baseline (speedup 1.0000x reference)
#include <cuda_runtime.h>
#include <math.h>

// Problem constants
#define BB 4
#define SS 256
#define NN 512
#define RR 32
#define LL (NN * RR)          // 16384 output samples per batch
#define NCHUNK 8
#define S_PER_CHUNK (SS / NCHUNK)  // 32

// Reference-matching constants:
// ref: omegas = freqs_up * fl32(2*pi/44100);  phases % fl32(2*pi)
#define TWO_PI_D 6.283185307179586
#define CF_F  ((float)(TWO_PI_D / 44100.0))    // fp32 omega scale, as jax computes it
#define CMOD_F ((float)TWO_PI_D)               // fp32 2*pi used in the ref's mod
#define CMOD_D ((double)CMOD_F)
#define INV_CMOD_D (1.0 / (double)CMOD_F)

// Scratch (no cudaMalloc allowed)
__device__ double d_base[BB * SS * NN];          // P[i] = 32*Q[i] + 16*g_i   (4 MB)
__device__ float  d_part[BB * NCHUNK * LL];      // per-sine-chunk partial sums (2 MB)

// ---------------------------------------------------------------------------
// Kernel 1: per (b,s) sequence, prefix-sum the 512 control-point omegas in
// double and store segment base phases. One CTA of 512 threads per sequence.
// ---------------------------------------------------------------------------
__global__ void k_base(const float* __restrict__ freq) {
    int seq = blockIdx.x;           // b*SS + s
    int i   = threadIdx.x;          // control point index 0..511
    __shared__ double sh[NN];

    float f  = freq[seq * NN + i];
    double g = (double)f * (double)CF_F;
    sh[i] = g;
    __syncthreads();

    // Hillis-Steele inclusive scan (double)
    #pragma unroll
    for (int off = 1; off < NN; off <<= 1) {
        double add = (i >= off) ? sh[i - off] : 0.0;
        double v   = sh[i];
        __syncthreads();
        sh[i] = v + add;
        __syncthreads();
    }
    double q_incl = sh[i];                 // Q[i] + g_i
    // base = 32*Q_excl + 16*g = 32*Q_incl - 16*g
    d_base[seq * NN + i] = 32.0 * q_incl - 16.0 * g;
}

// ---------------------------------------------------------------------------
// Kernel 2: main synthesis. Thread = (b, sine-chunk c, output sample t).
// gid = (b*NCHUNK + c)*LL + t  so warp lanes are consecutive t (broadcast loads).
// Each thread loops over its 32 sines, computes the closed-form phase in
// double, mods by fl32(2*pi), sin in fp32, lerps the amplitude, accumulates.
// ---------------------------------------------------------------------------
__global__ void k_main(const float* __restrict__ freq,
                       const float* __restrict__ amp) {
    int gid = blockIdx.x * blockDim.x + threadIdx.x;
    int t   = gid & (LL - 1);
    int bc  = gid >> 14;            // b*NCHUNK + c
    int c   = bc & (NCHUNK - 1);
    int b   = bc >> 3;
    int s0  = c * S_PER_CHUNK;

    // Segment decomposition of t (mode: 0=head, 1=mid, 2=tail)
    int mode;
    int i;          // control segment index
    double u;       // local sample count (j+1)
    float w = 0.0f; // amplitude lerp weight
    if (t < 16) {
        mode = 0; i = 0; u = (double)(t + 1);
    } else if (t >= LL - 16) {
        mode = 2; i = NN - 1; u = (double)(t - (LL - 16) + 1);
    } else {
        int tt = t - 16;
        i = tt >> 5;
        int j = tt & 31;
        u = (double)(j + 1);
        w = (float)(2 * j + 1) * (1.0f / 64.0f);   // (j+0.5)/32, exact in fp32
        mode = 1;
    }
    double u2_64 = (u * u) * (1.0 / 64.0);
    float  omw   = 1.0f - w;

    const float*  fp = freq   + ((size_t)(b * SS + s0)) * NN + i;
    const float*  ap = amp    + ((size_t)(b * SS + s0)) * NN + i;
    const double* bp = d_base + ((size_t)(b * SS + s0)) * NN + i;

    float acc = 0.0f;
    #pragma unroll 4
    for (int k = 0; k < S_PER_CHUNK; k++) {
        float  fi = fp[0];
        double gi = (double)fi * (double)CF_F;
        double phi;
        float  a;
        if (mode == 1) {
            float  fip = fp[1];
            double gip = (double)fip * (double)CF_F;
            phi = bp[0] + u * gi + (gip - gi) * u2_64;
            float ai  = ap[0];
            float aip = ap[1];
            a = ai * omw + aip * w;          // ref: x[i0]*(1-w)+x[i1]*w
        } else if (mode == 0) {
            phi = u * gi;                    // P=0, constant f[0] head
            a   = ap[0];
        } else {
            phi = bp[0] + u * gi;            // tail: base[511] + u*g[511]
            a   = ap[0];
        }
        // phase mod fl32(2*pi), computed in double (matches ref's exact fmod
        // by the float-rounded 2*pi up to a negligible sub-ulp residue)
        double q = floor(phi * INV_CMOD_D);
        float  r = (float)(phi - q * CMOD_D);
        acc = fmaf(a, __sinf(r), acc);

        fp += NN; ap += NN; bp += NN;
    }
    d_part[gid] = acc;
}

// ---------------------------------------------------------------------------
// Kernel 3: deterministic 8-way reduction of sine-chunk partials -> output.
// Fixed summation order => bitwise-deterministic output (no float atomics).
// ---------------------------------------------------------------------------
__global__ void k_reduce(float* __restrict__ out) {
    int gid = blockIdx.x * blockDim.x + threadIdx.x;  // b*LL + t
    int b = gid >> 14;
    int t = gid & (LL - 1);
    const float* p = d_part + ((size_t)(b * NCHUNK)) * LL + t;
    float s = 0.0f;
    #pragma unroll
    for (int c = 0; c < NCHUNK; c++) {
        s += p[c * LL];
    }
    out[gid] = s;
}

// ---------------------------------------------------------------------------
extern "C" void kernel_launch(void* const* d_in, const int* in_sizes, int n_in,
                              void* d_out, int out_size) {
    const float* freq = (const float*)d_in[0];
    const float* amp  = (const float*)d_in[1];
    float* out = (float*)d_out;

    // K1: 1024 sequences, 512 threads each (control-point prefix in double)
    k_base<<<BB * SS, NN>>>(freq);

    // K2: B * NCHUNK * LL threads = 524288
    k_main<<<(BB * NCHUNK * LL) / 256, 256>>>(freq, amp);

    // K3: B * LL threads = 65536
    k_reduce<<<(BB * LL) / 256, 256>>>(out);
}

// round 2
// speedup vs baseline: 10.3098x; 10.3098x over previous
#include <cuda_runtime.h>
#include <math.h>

// Problem constants
#define BB 4
#define SS 256
#define NN 512
#define RR 32
#define LL (NN * RR)          // 16384 output samples per batch
#define NCHUNK 8
#define S_PER_CHUNK (SS / NCHUNK)  // 32
#define NE 513                // extended segments: head(1) + 512 entries

// Reference-matching constants
#define TWO_PI_D 6.283185307179586
#define CF_F  ((float)(TWO_PI_D / 44100.0))    // fp32 omega scale (as jax computes)
#define CMOD_F ((float)TWO_PI_D)               // fp32 2*pi used in the ref's mod
#define CMOD_D ((double)CMOD_F)
#define INV_CMOD_D (1.0 / (double)CMOD_F)
#define INV_CMOD_F ((float)(1.0 / (double)CMOD_F))

// Scratch (no cudaMalloc allowed)
__device__ float4 d_tab[BB * SS * NE];       // {base_mod, g, dg/64, a}  (~8.4 MB)
__device__ float  d_da [BB * SS * NE];       // a_{i+1}-a_i              (~2.1 MB)
__device__ float  d_part[BB * NCHUNK * LL];  // per-sine-chunk partials  (2 MB)

// ---------------------------------------------------------------------------
// Kernel 1: per (b,s) sequence, double-precision prefix of omegas via shfl
// scan, then emit the fp32 per-segment table with base phase pre-reduced
// mod fl32(2*pi) (reduction done in double to match the reference's wrap).
// One CTA of 512 threads per sequence.
// ---------------------------------------------------------------------------
__global__ void k_base(const float* __restrict__ freq,
                       const float* __restrict__ amp) {
    int seq  = blockIdx.x;          // b*SS + s
    int i    = threadIdx.x;         // control point index 0..511
    int lane = i & 31;
    int wid  = i >> 5;

    float f = freq[seq * NN + i];
    float a = amp [seq * NN + i];
    double g = (double)f * (double)CF_F;

    // warp-level inclusive scan (double)
    double x = g;
    #pragma unroll
    for (int off = 1; off < 32; off <<= 1) {
        double y = __shfl_up_sync(0xFFFFFFFFu, x, off);
        if (lane >= off) x += y;
    }

    __shared__ double wsum[16];
    if (lane == 31) wsum[wid] = x;
    __syncthreads();
    if (wid == 0) {
        double y = (lane < 16) ? wsum[lane] : 0.0;
        #pragma unroll
        for (int off = 1; off < 16; off <<= 1) {
            double z = __shfl_up_sync(0xFFFFFFFFu, y, off);
            if (lane >= off) y += z;
        }
        if (lane < 16) wsum[lane] = y;
    }
    __syncthreads();
    double Qi = x + ((wid > 0) ? wsum[wid - 1] : 0.0);   // inclusive prefix

    // base phase at segment start: P = 32*Q_excl + 16*g = 32*Q_incl - 16*g
    double P = 32.0 * Qi - 16.0 * g;
    double m = P - floor(P * INV_CMOD_D) * CMOD_D;       // mod fl32(2*pi), in double

    float fnext = (i < NN - 1) ? freq[seq * NN + i + 1] : f;
    float anext = (i < NN - 1) ? amp [seq * NN + i + 1] : a;
    float gf  = f * CF_F;
    float gnf = fnext * CF_F;
    float dg64 = (i < NN - 1) ? (gnf - gf) * (1.0f / 64.0f) : 0.0f;
    float da   = (i < NN - 1) ? (anext - a) : 0.0f;

    size_t tb = (size_t)seq * NE;
    d_tab[tb + i + 1] = make_float4((float)m, gf, dg64, a);
    d_da [tb + i + 1] = da;
    if (i == 0) {                       // head segment: base 0, constant f0/a0
        d_tab[tb] = make_float4(0.0f, gf, 0.0f, a);
        d_da [tb] = 0.0f;
    }
}

// ---------------------------------------------------------------------------
// Kernel 2: main synthesis, all-fp32 inner loop. Thread = (b, chunk c, t).
// Lanes are consecutive t so the table loads are near-broadcast.
// ---------------------------------------------------------------------------
__global__ void k_main() {
    int gid = blockIdx.x * blockDim.x + threadIdx.x;
    int t   = gid & (LL - 1);
    int bc  = gid >> 14;            // b*NCHUNK + c
    int c   = bc & (NCHUNK - 1);
    int b   = bc >> 3;

    // extended segment index e, local sample count u = j+1, amp weight w
    int e, uj;
    if (t < 16)            { e = 0;                uj = t + 1; }
    else if (t >= LL - 16) { e = NN;               uj = t - (LL - 16) + 1; }
    else { int tt = t - 16; e = 1 + (tt >> 5);     uj = (tt & 31) + 1; }

    float u  = (float)uj;
    float u2 = u * u;
    float w  = (float)(2 * uj - 1) * (1.0f / 64.0f);  // (j+0.5)/32

    size_t rowbase = (size_t)(b * SS + c * S_PER_CHUNK) * NE + e;
    const float4* tp = d_tab + rowbase;
    const float*  dp = d_da  + rowbase;

    float acc = 0.0f;
    #pragma unroll 8
    for (int k = 0; k < S_PER_CHUNK; k++) {
        float4 v  = tp[0];
        float  da = dp[0];
        float phi = fmaf(u,  v.y, v.x);     // base + u*g
        phi       = fmaf(u2, v.z, phi);     // + (dg/64)*u^2
        float amp = fmaf(w,  da,  v.w);     // a + w*da
        float q = floorf(phi * INV_CMOD_F);
        float r = fmaf(q, -CMOD_F, phi);    // phi mod fl32(2*pi)
        acc = fmaf(amp, __sinf(r), acc);
        tp += NE; dp += NE;
    }
    d_part[gid] = acc;
}

// ---------------------------------------------------------------------------
// Kernel 3: deterministic 8-way reduction of sine-chunk partials -> output.
// ---------------------------------------------------------------------------
__global__ void k_reduce(float* __restrict__ out) {
    int gid = blockIdx.x * blockDim.x + threadIdx.x;  // b*LL + t
    int b = gid >> 14;
    int t = gid & (LL - 1);
    const float* p = d_part + ((size_t)(b * NCHUNK)) * LL + t;
    float s = 0.0f;
    #pragma unroll
    for (int c = 0; c < NCHUNK; c++) s += p[c * LL];
    out[gid] = s;
}

// ---------------------------------------------------------------------------
extern "C" void kernel_launch(void* const* d_in, const int* in_sizes, int n_in,
                              void* d_out, int out_size) {
    const float* freq = (const float*)d_in[0];
    const float* amp  = (const float*)d_in[1];
    float* out = (float*)d_out;

    k_base<<<BB * SS, NN>>>(freq, amp);                 // 1024 blocks x 512
    k_main<<<(BB * NCHUNK * LL) / 256, 256>>>();        // 524288 threads
    k_reduce<<<(BB * LL) / 256, 256>>>(out);            // 65536 threads
}

// round 3
// speedup vs baseline: 16.4863x; 1.5991x over previous
#include <cuda_runtime.h>
#include <math.h>

// Problem constants
#define BB 4
#define SS 256
#define NN 512
#define RR 32
#define LL (NN * RR)          // 16384 output samples per batch
#define NCHUNK 8
#define S_PER_CHUNK (SS / NCHUNK)  // 32
#define NE 513                // extended segments: head(1) + 512 entries

// Reference-matching constants
#define TWO_PI_D 6.283185307179586
#define CF_F  ((float)(TWO_PI_D / 44100.0))    // fp32 omega scale (as jax computes)
#define CMOD_F ((float)TWO_PI_D)               // fp32 2*pi used in the ref's mod
#define INV_CMOD_F ((float)(1.0 / (double)((float)TWO_PI_D)))

// Scratch (no cudaMalloc allowed)
__device__ float4 d_tab[BB * SS * NE];       // {base_mod, g, dg/64, a}
__device__ float  d_da [BB * SS * NE];       // a_{i+1}-a_i

// ---------------------------------------------------------------------------
// double-float (two-fp32) compensated arithmetic.
// Safe under nvcc: no FP reassociation; contraction can't touch add-only chains.
// ---------------------------------------------------------------------------
__device__ __forceinline__ float2 two_sum(float a, float b) {
    float s  = a + b;
    float bb = s - a;
    float e  = (a - (s - bb)) + (b - bb);
    return make_float2(s, e);
}
__device__ __forceinline__ float2 df_add(float2 a, float2 b) {
    float2 s = two_sum(a.x, b.x);
    float lo = s.y + (a.y + b.y);
    float hi = s.x + lo;
    lo = lo - (hi - s.x);
    return make_float2(hi, lo);
}

// ---------------------------------------------------------------------------
// Kernel 1: per (b,s) sequence, df-precision prefix of omegas via shfl scan,
// then emit the fp32 per-segment table with base phase reduced mod fl32(2*pi).
// One CTA of 512 threads per sequence. ZERO fp64 instructions.
// ---------------------------------------------------------------------------
__global__ void k_base(const float* __restrict__ freq,
                       const float* __restrict__ amp) {
    int seq  = blockIdx.x;          // b*SS + s
    int i    = threadIdx.x;         // control point index 0..511
    int lane = i & 31;
    int wid  = i >> 5;

    float f = freq[seq * NN + i];
    float a = amp [seq * NN + i];

    // exact product split: (g_hi, g_lo) == (double)f * (double)CF_F exactly
    float g_hi = f * CF_F;
    float g_lo = fmaf(f, CF_F, -g_hi);
    float2 x = make_float2(g_hi, g_lo);

    // warp-level inclusive scan (df)
    #pragma unroll
    for (int off = 1; off < 32; off <<= 1) {
        float yh = __shfl_up_sync(0xFFFFFFFFu, x.x, off);
        float yl = __shfl_up_sync(0xFFFFFFFFu, x.y, off);
        if (lane >= off) x = df_add(x, make_float2(yh, yl));
    }

    __shared__ float2 wsum[16];
    if (lane == 31) wsum[wid] = x;
    __syncthreads();
    if (wid == 0) {
        float2 y = (lane < 16) ? wsum[lane] : make_float2(0.0f, 0.0f);
        #pragma unroll
        for (int off = 1; off < 16; off <<= 1) {
            float zh = __shfl_up_sync(0xFFFFFFFFu, y.x, off);
            float zl = __shfl_up_sync(0xFFFFFFFFu, y.y, off);
            if (lane >= off) y = df_add(y, make_float2(zh, zl));
        }
        if (lane < 16) wsum[lane] = y;
    }
    __syncthreads();
    float2 Q = x;
    if (wid > 0) Q = df_add(Q, wsum[wid - 1]);          // inclusive prefix (df)

    // base phase: P = 32*Q_incl - 16*g  (scalings by 32/16 are exact)
    float2 Q32  = make_float2(32.0f * Q.x, 32.0f * Q.y);
    float2 g16n = make_float2(-16.0f * g_hi, -16.0f * g_lo);
    float2 P = df_add(Q32, g16n);

    // reduce mod fl32(2*pi). Off-by-one wrap costs only |2pi - fl32(2pi)| ~ 2.7e-7.
    float q = floorf(P.x * INV_CMOD_F);
    float m = fmaf(-q, CMOD_F, P.x) + P.y;

    float fnext = (i < NN - 1) ? freq[seq * NN + i + 1] : f;
    float anext = (i < NN - 1) ? amp [seq * NN + i + 1] : a;
    float dg64 = (i < NN - 1) ? (fnext * CF_F - g_hi) * (1.0f / 64.0f) : 0.0f;
    float da   = (i < NN - 1) ? (anext - a) : 0.0f;

    size_t tb = (size_t)seq * NE;
    d_tab[tb + i + 1] = make_float4(m, g_hi, dg64, a);
    d_da [tb + i + 1] = da;
    if (i == 0) {                       // head segment: base 0, constant f0/a0
        d_tab[tb] = make_float4(0.0f, g_hi, 0.0f, a);
        d_da [tb] = 0.0f;
    }
}

// ---------------------------------------------------------------------------
// Kernel 2: fused synthesis + reduction. Block = 256 threads = 8 sine-chunks
// x 32 consecutive t samples. Each thread sums its chunk's 32 sines for its
// t; an 8-way fixed-order smem reduction produces the final output directly.
// Bitwise deterministic (no float atomics, fixed order).
// ---------------------------------------------------------------------------
__global__ void k_main(float* __restrict__ out) {
    int lane = threadIdx.x & 31;       // t offset within the block's window
    int c    = threadIdx.x >> 5;       // sine chunk 0..7
    int tblk = blockIdx.x & (LL / 32 - 1);
    int b    = blockIdx.x >> 9;        // LL/32 = 512 blocks per batch
    int t    = tblk * 32 + lane;

    // extended segment index e, local sample count u = j+1, amp weight w
    int e, uj;
    if (t < 16)            { e = 0;                uj = t + 1; }
    else if (t >= LL - 16) { e = NN;               uj = t - (LL - 16) + 1; }
    else { int tt = t - 16; e = 1 + (tt >> 5);     uj = (tt & 31) + 1; }

    float u  = (float)uj;
    float u2 = u * u;
    float w  = (float)(2 * uj - 1) * (1.0f / 64.0f);  // (j+0.5)/32

    size_t rowbase = (size_t)(b * SS + c * S_PER_CHUNK) * NE + e;
    const float4* tp = d_tab + rowbase;
    const float*  dp = d_da  + rowbase;

    float acc = 0.0f;
    #pragma unroll 8
    for (int k = 0; k < S_PER_CHUNK; k++) {
        float4 v  = tp[0];
        float  da = dp[0];
        float phi = fmaf(u,  v.y, v.x);     // base + u*g
        phi       = fmaf(u2, v.z, phi);     // + (dg/64)*u^2
        float amp = fmaf(w,  da,  v.w);     // a + w*da
        float q = floorf(phi * INV_CMOD_F);
        float r = fmaf(q, -CMOD_F, phi);    // phi mod fl32(2*pi)
        acc = fmaf(amp, __sinf(r), acc);
        tp += NE; dp += NE;
    }

    __shared__ float sdata[NCHUNK][32];
    sdata[c][lane] = acc;
    __syncthreads();
    if (c == 0) {
        float s = sdata[0][lane];
        #pragma unroll
        for (int cc = 1; cc < NCHUNK; cc++) s += sdata[cc][lane];
        out[b * LL + t] = s;
    }
}

// ---------------------------------------------------------------------------
extern "C" void kernel_launch(void* const* d_in, const int* in_sizes, int n_in,
                              void* d_out, int out_size) {
    const float* freq = (const float*)d_in[0];
    const float* amp  = (const float*)d_in[1];
    float* out = (float*)d_out;

    k_base<<<BB * SS, NN>>>(freq, amp);            // 1024 blocks x 512
    k_main<<<BB * (LL / 32), 256>>>(out);          // 2048 blocks x 256
}